// round 13
// baseline (speedup 1.0000x reference)
#include <cuda_runtime.h>
#include <cuda_bf16.h>
#include <cstdint>

#define M_DIM 128
#define D_DIM 16
#define W_DIM 15
#define POS   (W_DIM*W_DIM*W_DIM*W_DIM)   // 50625
#define BATCH 4
#define ROWS  (BATCH*POS)                  // 202500
#define TILE_M 64
#define TILES ((ROWS + TILE_M - 1) / TILE_M)   // 3165
#define GRID_FUSED 456                         // 3 CTAs/SM x 152 SMs

// Globals written by prep (stream-ordered before fused kernel)
__device__ float         g_nk[256 * M_DIM];
__device__ __nv_bfloat16 g_Eh[M_DIM * M_DIM];   // bf16(M - I), row-major

// ---------------------------------------------------------------------------
__device__ __forceinline__ uint32_t smem_u32(const void* p) {
    uint32_t a;
    asm("{ .reg .u64 t; cvta.to.shared.u64 t, %1; cvt.u32.u64 %0, t; }"
        : "=r"(a) : "l"(p));
    return a;
}
__device__ __forceinline__ uint32_t pack_bf16(__nv_bfloat16 a, __nv_bfloat16 b) {
    return ((uint32_t)__bfloat16_as_ushort(b) << 16) | __bfloat16_as_ushort(a);
}
__device__ __forceinline__ void split2(float x, float y, uint32_t& hi, uint32_t& lo) {
    __nv_bfloat16 hx = __float2bfloat16_rn(x);
    __nv_bfloat16 hy = __float2bfloat16_rn(y);
    __nv_bfloat16 lx = __float2bfloat16_rn(x - __bfloat162float(hx));
    __nv_bfloat16 ly = __float2bfloat16_rn(y - __bfloat162float(hy));
    hi = pack_bf16(hx, hy);
    lo = pack_bf16(lx, ly);
}
__device__ __forceinline__ float2 bf16x2_to_f2(uint32_t v) {
    __nv_bfloat162 b;
    *(uint32_t*)&b = v;
    return __bfloat1622float2(b);
}
__device__ __forceinline__ void mma_bf16(float* c, const uint32_t* a, const uint32_t* b) {
    asm volatile(
        "mma.sync.aligned.m16n8k16.row.col.f32.bf16.bf16.f32 "
        "{%0,%1,%2,%3}, {%4,%5,%6,%7}, {%8,%9}, {%0,%1,%2,%3};"
        : "+f"(c[0]), "+f"(c[1]), "+f"(c[2]), "+f"(c[3])
        : "r"(a[0]), "r"(a[1]), "r"(a[2]), "r"(a[3]), "r"(b[0]), "r"(b[1]));
}
__device__ __forceinline__ void ldm_x4(uint32_t (&r)[4], uint32_t addr) {
    asm volatile("ldmatrix.sync.aligned.m8n8.x4.shared.b16 {%0,%1,%2,%3}, [%4];"
        : "=r"(r[0]), "=r"(r[1]), "=r"(r[2]), "=r"(r[3]) : "r"(addr));
}
#define CP_ASYNC_CG(dst, src) \
    asm volatile("cp.async.cg.shared.global [%0], [%1], 16;" \
                 :: "r"(dst), "l"(src) : "memory")
#define CP_ASYNC_COMMIT() asm volatile("cp.async.commit_group;" ::: "memory")
#define CP_ASYNC_WAIT0()  asm volatile("cp.async.wait_group 0;" ::: "memory")

// ---------------------------------------------------------------------------
// Prep: Nk table + E = bf16(M - I)
// ---------------------------------------------------------------------------
__global__ void prep_kernel(const float* __restrict__ Acoeff,
                            const float* __restrict__ Bbasis,
                            const float* __restrict__ Mmat) {
    int e = blockIdx.x * 256 + threadIdx.x;   // 0..49151
    if (e < 32768) {
        int idx = e >> 7, j = e & 127;
        g_nk[e] = Acoeff[j * 256 + idx] * Bbasis[idx * M_DIM + j];
    } else {
        int e2 = e - 32768;                    // 0..16383
        int r = e2 >> 7, c = e2 & 127;
        float v = Mmat[e2] - (r == c ? 1.0f : 0.0f);
        g_Eh[e2] = __float2bfloat16_rn(v);
    }
}

// ---------------------------------------------------------------------------
// SMEM layout (73728 B = 9 granules -> 3 CTAs/SM). ALL pitches 16B-aligned:
//  E    : 128 rows x 272B  (ldmatrix-safe; 68w%32=4 conflict-free phases)
//  A_hi : 2 K-half slots, 64 rows x 144B (36w%32=4)
//  A_lo : 64 rows x 256B row-major
//  ST   : 8 rows x 128 fp32 words, per-row rotation (col+16*row)&127
// ---------------------------------------------------------------------------
#define PITCH_E   272
#define PITCH_A   144
#define OFF_E     0
#define OFF_A0    (128 * PITCH_E)              // 34816
#define OFF_A1    (OFF_A0 + TILE_M * PITCH_A)  // 44032
#define OFF_ALO   (OFF_A1 + TILE_M * PITCH_A)  // 53248
#define OFF_ST    (OFF_ALO + TILE_M * 256)     // 69632
#define SMEM_TOTAL (OFF_ST + 8 * 128 * 4)      // 73728

__global__ void __launch_bounds__(256, 3)
fused_kernel(const float4* __restrict__ vec, float* __restrict__ out) {
    extern __shared__ char smem[];
    const uint32_t sb = smem_u32(smem);
    const int t    = threadIdx.x;
    const int wid  = t >> 5;
    const int lane = t & 31;
    const int wm = wid & 1;
    const int wn = wid >> 1;

    // E -> smem once per CTA
    {
        const char* eh = (const char*)g_Eh;
#pragma unroll
        for (int i = 0; i < 8; i++) {                  // 2048 x 16B chunks
            int e = t + i * 256;
            int r = e >> 4, c = e & 15;
            CP_ASYNC_CG(sb + OFF_E + (uint32_t)(r * PITCH_E + c * 16),
                        eh + r * 256 + c * 16);
        }
        CP_ASYNC_COMMIT();
    }

    const uint32_t eFrag = sb + OFF_E
        + (uint32_t)((wn * 32 + (lane & 7) + (lane >> 4) * 8) * PITCH_E
                     + ((lane >> 3) & 1) * 16);
    const uint32_t a0Frag = sb + OFF_A0
        + (uint32_t)((wm * 32 + (lane & 15)) * PITCH_A + (lane >> 4) * 16);
    const uint32_t a1Frag = a0Frag + (OFF_A1 - OFF_A0);

    const int g  = lane >> 2;
    const int cq = (lane & 3) * 2;

    const int S4 = 32, S3 = 512, S2 = 8192, S1 = 131072;  // float4 strides
    const long long SBATCH = (long long)S1 * D_DIM;

    for (int tile = blockIdx.x; tile < TILES; tile += GRID_FUSED) {
        const int row0 = tile * TILE_M;

        // ================= POOL: 2^4 mean -> smem A_hi/A_lo =================
        {
            const int q = lane;                // 8B channel chunk
            int r    = row0 + wid * 8;
            int rend = r + 8;
            for (int rr = (r < ROWS ? ROWS : r); rr < rend; rr++) {
                int lr = rr - row0;
                uint32_t ao = (q < 16 ? OFF_A0 : OFF_A1)
                              + lr * PITCH_A + (q & 15) * 8;
                *(uint2*)(smem + ao) = make_uint2(0u, 0u);
                *(uint2*)(smem + OFF_ALO + lr * 256 + q * 8) = make_uint2(0u, 0u);
            }
            int gend = rend < ROWS ? rend : ROWS;

            while (r < gend) {
                int b   = r / POS;
                int pos = r - b * POS;
                int k4  = pos % W_DIM;
                int r1  = pos / W_DIM;
                int k3  = r1 % W_DIM;
                int r2  = r1 / W_DIM;
                int k2  = r2 % W_DIM;
                int k1  = r2 / W_DIM;
                int segend = r + (W_DIM - k4);
                if (segend > gend) segend = gend;
                const int L = segend - r;

                const float4* p = vec + b * SBATCH + k1 * S1 + k2 * S2
                                      + k3 * S3 + k4 * S4 + q;
                const int co1 = S3, co2 = S2, co3 = S2 + S3;
                const int co4 = S1, co5 = S1 + S3, co6 = S1 + S2,
                          co7 = S1 + S2 + S3;

                float4 sp;
                {
                    float sx = 0.f, sy = 0.f, sz = 0.f, sw = 0.f;
                    float4 v;
                    v = __ldg(p);        sx += v.x; sy += v.y; sz += v.z; sw += v.w;
                    v = __ldg(p + co1);  sx += v.x; sy += v.y; sz += v.z; sw += v.w;
                    v = __ldg(p + co2);  sx += v.x; sy += v.y; sz += v.z; sw += v.w;
                    v = __ldg(p + co3);  sx += v.x; sy += v.y; sz += v.z; sw += v.w;
                    v = __ldg(p + co4);  sx += v.x; sy += v.y; sz += v.z; sw += v.w;
                    v = __ldg(p + co5);  sx += v.x; sy += v.y; sz += v.z; sw += v.w;
                    v = __ldg(p + co6);  sx += v.x; sy += v.y; sz += v.z; sw += v.w;
                    v = __ldg(p + co7);  sx += v.x; sy += v.y; sz += v.z; sw += v.w;
                    sp = make_float4(sx, sy, sz, sw);
                }
                for (int j = 1; j <= L; j++) {
                    const float4* pj = p + j * S4;
                    float sx = 0.f, sy = 0.f, sz = 0.f, sw = 0.f;
                    float4 v;
                    v = __ldg(pj);       sx += v.x; sy += v.y; sz += v.z; sw += v.w;
                    v = __ldg(pj + co1); sx += v.x; sy += v.y; sz += v.z; sw += v.w;
                    v = __ldg(pj + co2); sx += v.x; sy += v.y; sz += v.z; sw += v.w;
                    v = __ldg(pj + co3); sx += v.x; sy += v.y; sz += v.z; sw += v.w;
                    v = __ldg(pj + co4); sx += v.x; sy += v.y; sz += v.z; sw += v.w;
                    v = __ldg(pj + co5); sx += v.x; sy += v.y; sz += v.z; sw += v.w;
                    v = __ldg(pj + co6); sx += v.x; sy += v.y; sz += v.z; sw += v.w;
                    v = __ldg(pj + co7); sx += v.x; sy += v.y; sz += v.z; sw += v.w;

                    float ox = (sp.x + sx) * 0.0625f;
                    float oy = (sp.y + sy) * 0.0625f;
                    float oz = (sp.z + sz) * 0.0625f;
                    float ow = (sp.w + sw) * 0.0625f;
                    sp = make_float4(sx, sy, sz, sw);

                    uint2 hv, lv;
                    split2(ox, oy, hv.x, lv.x);
                    split2(oz, ow, hv.y, lv.y);
                    int lr = r + j - 1 - row0;
                    uint32_t ao = (q < 16 ? OFF_A0 : OFF_A1)
                                  + lr * PITCH_A + (q & 15) * 8;
                    *(uint2*)(smem + ao) = hv;
                    *(uint2*)(smem + OFF_ALO + lr * 256 + q * 8) = lv;
                }
                r = segend;
            }
        }
        CP_ASYNC_WAIT0();                 // E ready (no-op after 1st tile)
        __syncthreads();                  // pool writes visible to MMA

        // ================= MMA: acc = A_hi @ E^T =================
        float acc[2][4][4];
#pragma unroll
        for (int mt = 0; mt < 2; mt++)
#pragma unroll
            for (int nt = 0; nt < 4; nt++)
#pragma unroll
                for (int i = 0; i < 4; i++) acc[mt][nt][i] = 0.f;

#pragma unroll
        for (int h = 0; h < 2; h++) {
            const uint32_t aF = h ? a1Frag : a0Frag;
#pragma unroll
            for (int ks = 0; ks < 4; ks++) {
                const uint32_t koff = ks * 32;
                const uint32_t kb   = h * 128 + ks * 32;
                uint32_t ah[2][4], ehf[2][4];
                ldm_x4(ah[0], aF + koff);
                ldm_x4(ah[1], aF + 16 * PITCH_A + koff);
                ldm_x4(ehf[0], eFrag + kb);
                ldm_x4(ehf[1], eFrag + 16 * PITCH_E + kb);
#pragma unroll
                for (int mt = 0; mt < 2; mt++)
#pragma unroll
                    for (int nt = 0; nt < 4; nt++)
                        mma_bf16(acc[mt][nt], ah[mt], &ehf[nt >> 1][(nt & 1) * 2]);
            }
        }

        // ========= EPILOGUE: 8 phases x 8 rows; warp-per-row reads =========
        // out = Nk - (A_hi + A_lo) - acc. Staging rows rotated by 16*row.
        const int row0t = tile * TILE_M;
#pragma unroll
        for (int p = 0; p < 8; p++) {
            const int mt = (p >> 1) & 1;
            const int h8 = p & 1;
            if (wm == (p >> 2)) {          // stage this phase's fp32 acc
#pragma unroll
                for (int nt = 0; nt < 4; nt++) {
                    int col = wn * 32 + nt * 8 + cq;
                    int w0  = (col + g * 16) & 127;
                    float2 v;
                    v.x = acc[mt][nt][h8 * 2 + 0];
                    v.y = acc[mt][nt][h8 * 2 + 1];
                    *(float2*)(smem + OFF_ST + (g * 128 + w0) * 4) = v;
                }
            }
            __syncthreads();
            {
                int lr  = p * 8 + wid;     // warp wid handles staged row wid
                int row = row0t + lr;
                int c4  = lane;            // 4-col chunk
                if (row < ROWS) {
                    int pos = row % POS;
                    int k4 = pos % W_DIM;
                    int q1 = pos / W_DIM;
                    int k3 = q1 % W_DIM;
                    int q2 = q1 / W_DIM;
                    int k2 = q2 % W_DIM;
                    int k1 = q2 / W_DIM;
                    int idx = (((k1 & 3) * 4 + (k2 & 3)) * 4 + (k3 & 3)) * 4
                              + (k4 & 3);
                    float4 nk = __ldg((const float4*)(g_nk + idx * M_DIM + c4 * 4));
                    uint2 ph = *(const uint2*)(smem
                        + (c4 < 16 ? OFF_A0 : OFF_A1) + lr * PITCH_A
                        + (c4 & 15) * 8);
                    uint2 pl = *(const uint2*)(smem + OFF_ALO + lr * 256 + c4 * 8);
                    int w0 = (c4 * 4 + wid * 16) & 127;
                    float4 st = *(const float4*)(smem + OFF_ST
                                                 + (wid * 128 + w0) * 4);
                    float2 h0 = bf16x2_to_f2(ph.x), l0 = bf16x2_to_f2(pl.x);
                    float2 h1 = bf16x2_to_f2(ph.y), l1 = bf16x2_to_f2(pl.y);
                    float4 o;
                    o.x = nk.x - (h0.x + l0.x) - st.x;
                    o.y = nk.y - (h0.y + l0.y) - st.y;
                    o.z = nk.z - (h1.x + l1.x) - st.z;
                    o.w = nk.w - (h1.y + l1.y) - st.w;
                    *(float4*)(out + (size_t)row * M_DIM + c4 * 4) = o;
                }
            }
            __syncthreads();   // staging reuse next phase / A reuse next tile
        }
    }
}

// ---------------------------------------------------------------------------
extern "C" void kernel_launch(void* const* d_in, const int* in_sizes, int n_in,
                              void* d_out, int out_size) {
    const float* vec    = (const float*)d_in[0];   // (4,16,16,16,16,128)
    const float* Mmat   = (const float*)d_in[1];   // (128,128)
    const float* Acoeff = (const float*)d_in[2];   // (128,256)
    const float* Bbasis = (const float*)d_in[3];   // (256,128)
    float* out = (float*)d_out;                    // (4, 50625, 128)

    cudaFuncSetAttribute(fused_kernel,
                         cudaFuncAttributeMaxDynamicSharedMemorySize,
                         SMEM_TOTAL);

    prep_kernel<<<192, 256>>>(Acoeff, Bbasis, Mmat);
    fused_kernel<<<GRID_FUSED, 256, SMEM_TOTAL>>>((const float4*)vec, out);
}